// round 2
// baseline (speedup 1.0000x reference)
#include <cuda_runtime.h>
#include <cstdint>
#include <cstdio>

#define NN 100000
#define EE 1600000

// ---------------------------------------------------------------------------
// Static device scratch (no allocation allowed).
// ---------------------------------------------------------------------------
__device__ __align__(256) float g_deg[NN];          // deg -> dinv (in place)
__device__ __align__(256) float g_en [EE];          // edge_norm
__device__ __align__(256) float g_xp [NN * 36];     // x padded 35->36
__device__ __align__(256) float g_p0 [NN * 36];     // agg(x)
__device__ __align__(256) float g_a1 [NN * 336];    // relu(conv1)
__device__ __align__(256) float g_t2 [NN * 168];    // a1 @ W2
__device__ __align__(256) float g_p2 [NN * 168];    // agg(t2)
__device__ __align__(256) float g_t3 [NN * 84];
__device__ __align__(256) float g_p3 [NN * 84];
__device__ __align__(256) float g_t4 [NN * 42];
__device__ __align__(256) float g_p4 [NN * 42];
__device__ __align__(256) float g_a4 [NN * 42];     // relu(p4 + b4)
__device__ __align__(256) float g_p5 [NN * 42];     // agg(a4)

// ---------------------------------------------------------------------------
// Packed f32x2 helpers (Blackwell FFMA2 — only reachable via PTX)
// ---------------------------------------------------------------------------
__device__ __forceinline__ uint64_t pack2(float lo, float hi) {
    uint64_t r;
    asm("mov.b64 %0, {%1, %2};" : "=l"(r) : "f"(lo), "f"(hi));
    return r;
}
__device__ __forceinline__ void unpack2(uint64_t v, float& lo, float& hi) {
    asm("mov.b64 {%0, %1}, %2;" : "=f"(lo), "=f"(hi) : "l"(v));
}
__device__ __forceinline__ void ffma2(uint64_t& d, uint64_t a, uint64_t b) {
    asm("fma.rn.f32x2 %0, %1, %2, %3;" : "=l"(d) : "l"(a), "l"(b), "l"(d));
}

// ---------------------------------------------------------------------------
// Vector reductions
// ---------------------------------------------------------------------------
__device__ __forceinline__ void red_add4(float* a, float4 v) {
    asm volatile("red.global.add.v4.f32 [%0], {%1,%2,%3,%4};"
                 :: "l"(a), "f"(v.x), "f"(v.y), "f"(v.z), "f"(v.w) : "memory");
}
__device__ __forceinline__ void red_add2(float* a, float2 v) {
    asm volatile("red.global.add.v2.f32 [%0], {%1,%2};"
                 :: "l"(a), "f"(v.x), "f"(v.y) : "memory");
}

// ---------------------------------------------------------------------------
// Degree / normalization
// ---------------------------------------------------------------------------
__global__ void k_deg_init(float* deg) {
    int i = blockIdx.x * blockDim.x + threadIdx.x;
    if (i < NN) deg[i] = 1.0f;
}
__global__ void k_deg_count(const int* __restrict__ dst, float* deg) {
    int e = blockIdx.x * blockDim.x + threadIdx.x;
    if (e < EE) atomicAdd(&deg[dst[e]], 1.0f);
}
__global__ void k_rsqrt(float* deg) {
    int i = blockIdx.x * blockDim.x + threadIdx.x;
    if (i < NN) deg[i] = rsqrtf(deg[i]);
}
__global__ void k_edge_norm(const int* __restrict__ src, const int* __restrict__ dst,
                            const float* __restrict__ dinv, float* __restrict__ en) {
    int e = blockIdx.x * blockDim.x + threadIdx.x;
    if (e < EE) en[e] = dinv[src[e]] * dinv[dst[e]];
}

// pad x [N,35] -> xp [N,36] and p0 = xp * dinv^2 (fused)
__global__ void k_pad_pinit(const float* __restrict__ x, const float* __restrict__ dinv,
                            float* __restrict__ xp, float* __restrict__ p0) {
    int i = blockIdx.x * blockDim.x + threadIdx.x;
    if (i >= NN * 36) return;
    int n = i / 36, c = i - n * 36;
    float v = (c < 35) ? x[(size_t)n * 35 + c] : 0.0f;
    xp[i] = v;
    float s = dinv[n];
    p0[i] = v * s * s;
}

// a4 = relu(p4 + b4); p5 = a4 * dinv^2 (fused)
__global__ void k_relu_bias_pinit(const float* __restrict__ p4, const float* __restrict__ b4,
                                  const float* __restrict__ dinv,
                                  float* __restrict__ a4, float* __restrict__ p5) {
    int i = blockIdx.x * blockDim.x + threadIdx.x;
    if (i >= NN * 42) return;
    int n = i / 42;
    float v = fmaxf(p4[i] + b4[i % 42], 0.0f);
    a4[i] = v;
    float s = dinv[n];
    p5[i] = v * s * s;
}

// ---------------------------------------------------------------------------
// Edge scatter: p[dst] += t[src] * en[e], vectorized atomics.
// ---------------------------------------------------------------------------
template <int D, int VEC>
__global__ void __launch_bounds__(252)
k_scatter(const int* __restrict__ src, const int* __restrict__ dst,
          const float* __restrict__ en, const float* __restrict__ t,
          float* __restrict__ p) {
    constexpr int GROUP = D / VEC;
    constexpr int EPB = 252 / GROUP;
    int lane = threadIdx.x;
    int g = lane / GROUP;
    int c = lane - g * GROUP;
    long e = (long)blockIdx.x * EPB + g;
    if (e >= EE) return;
    int s = src[e];
    int d = dst[e];
    float w = en[e];
    if (VEC == 4) {
        float4 v = *(const float4*)(t + (size_t)s * D + c * 4);
        v.x *= w; v.y *= w; v.z *= w; v.w *= w;
        red_add4(p + (size_t)d * D + c * 4, v);
    } else {
        float2 v = *(const float2*)(t + (size_t)s * D + c * 2);
        v.x *= w; v.y *= w;
        red_add2(p + (size_t)d * D + c * 2, v);
    }
}

// ---------------------------------------------------------------------------
// f32x2 GEMM: C[M,Nd] = f(A) @ B, 128x64 tile, 256 threads, 8x4 microtile.
// Row-paired accumulators in packed f32x2; B tile stored pre-duplicated.
// Optional: IN_RELU  -> a = relu(A + binA) applied at A-tile load
//           OUT_RELU -> c = relu(c + bout)
//           WRITE_P  -> also store P = C * dinv[row]^2 (GCN self-loop init)
// ---------------------------------------------------------------------------
template <bool IN_RELU, bool OUT_RELU, bool WRITE_P>
__global__ void __launch_bounds__(256)
k_gemm2(const float* __restrict__ A, int lda, const float* __restrict__ binA,
        const float* __restrict__ B, const float* __restrict__ bout,
        float* __restrict__ C, float* __restrict__ P, const float* __restrict__ dinv,
        int M, int K, int Nd) {
    __shared__ uint64_t As64[16][65];   // [kk][rowpair], floats at kk*130 + row
    __shared__ uint64_t Bsd[16][64];    // [kk][col] duplicated {b,b}

    int tid = threadIdx.x;
    int tx = tid & 15;        // col group: 4 cols
    int ty = tid >> 4;        // row group: 8 rows = 4 pairs
    int row0 = blockIdx.x * 128;
    int col0 = blockIdx.y * 64;
    float* Asf = (float*)As64;

    uint64_t acc[4][4];
#pragma unroll
    for (int i = 0; i < 4; i++)
#pragma unroll
        for (int j = 0; j < 4; j++) acc[i][j] = 0ull;

    for (int k0 = 0; k0 < K; k0 += 16) {
        // A tile: 128 rows x 16 k, transpose into pair-interleaved k-major
#pragma unroll
        for (int l = 0; l < 8; l++) {
            int idx = tid + l * 256;
            int kk = idx & 15, rr = idx >> 4;
            int grow = row0 + rr, gk = k0 + kk;
            float a = 0.0f;
            if (grow < M && gk < K) {
                a = A[(size_t)grow * lda + gk];
                if (IN_RELU) a = fmaxf(a + binA[gk], 0.0f);
            }
            Asf[kk * 130 + rr] = a;
        }
        // B tile: 16 k x 64 cols, duplicated
#pragma unroll
        for (int l = 0; l < 4; l++) {
            int idx = tid + l * 256;
            int cc = idx & 63, kk = idx >> 6;
            int gk = k0 + kk, gc = col0 + cc;
            float b = (gk < K && gc < Nd) ? B[(size_t)gk * Nd + gc] : 0.0f;
            Bsd[kk][cc] = pack2(b, b);
        }
        __syncthreads();
#pragma unroll
        for (int kk = 0; kk < 16; kk++) {
            uint64_t b0 = Bsd[kk][tx * 4 + 0];
            uint64_t b1 = Bsd[kk][tx * 4 + 1];
            uint64_t b2 = Bsd[kk][tx * 4 + 2];
            uint64_t b3 = Bsd[kk][tx * 4 + 3];
            uint64_t a0 = As64[kk][ty * 4 + 0];
            uint64_t a1 = As64[kk][ty * 4 + 1];
            uint64_t a2 = As64[kk][ty * 4 + 2];
            uint64_t a3 = As64[kk][ty * 4 + 3];
            ffma2(acc[0][0], a0, b0); ffma2(acc[0][1], a0, b1);
            ffma2(acc[0][2], a0, b2); ffma2(acc[0][3], a0, b3);
            ffma2(acc[1][0], a1, b0); ffma2(acc[1][1], a1, b1);
            ffma2(acc[1][2], a1, b2); ffma2(acc[1][3], a1, b3);
            ffma2(acc[2][0], a2, b0); ffma2(acc[2][1], a2, b1);
            ffma2(acc[2][2], a2, b2); ffma2(acc[2][3], a2, b3);
            ffma2(acc[3][0], a3, b0); ffma2(acc[3][1], a3, b1);
            ffma2(acc[3][2], a3, b2); ffma2(acc[3][3], a3, b3);
        }
        __syncthreads();
    }

    bool fullvec = (row0 + 127 < M) && (col0 + 63 < Nd) && ((Nd & 3) == 0);
    if (fullvec) {
#pragma unroll
        for (int i = 0; i < 4; i++) {
            int rlo = row0 + ty * 8 + 2 * i;
            float4 vl, vh;
            unpack2(acc[i][0], vl.x, vh.x);
            unpack2(acc[i][1], vl.y, vh.y);
            unpack2(acc[i][2], vl.z, vh.z);
            unpack2(acc[i][3], vl.w, vh.w);
            int col = col0 + tx * 4;
            if (OUT_RELU) {
                float4 bb = *(const float4*)(bout + col);
                vl.x = fmaxf(vl.x + bb.x, 0.f); vl.y = fmaxf(vl.y + bb.y, 0.f);
                vl.z = fmaxf(vl.z + bb.z, 0.f); vl.w = fmaxf(vl.w + bb.w, 0.f);
                vh.x = fmaxf(vh.x + bb.x, 0.f); vh.y = fmaxf(vh.y + bb.y, 0.f);
                vh.z = fmaxf(vh.z + bb.z, 0.f); vh.w = fmaxf(vh.w + bb.w, 0.f);
            }
            *(float4*)(C + (size_t)rlo * Nd + col) = vl;
            *(float4*)(C + (size_t)(rlo + 1) * Nd + col) = vh;
            if (WRITE_P) {
                float sl = dinv[rlo]; sl *= sl;
                float sh = dinv[rlo + 1]; sh *= sh;
                float4 pl = make_float4(vl.x * sl, vl.y * sl, vl.z * sl, vl.w * sl);
                float4 ph = make_float4(vh.x * sh, vh.y * sh, vh.z * sh, vh.w * sh);
                *(float4*)(P + (size_t)rlo * Nd + col) = pl;
                *(float4*)(P + (size_t)(rlo + 1) * Nd + col) = ph;
            }
        }
    } else {
#pragma unroll
        for (int i = 0; i < 4; i++) {
            int rlo = row0 + ty * 8 + 2 * i;
#pragma unroll
            for (int j = 0; j < 4; j++) {
                float lo, hi;
                unpack2(acc[i][j], lo, hi);
                int col = col0 + tx * 4 + j;
                if (col >= Nd) continue;
                if (rlo < M) {
                    float v = lo;
                    if (OUT_RELU) v = fmaxf(v + bout[col], 0.0f);
                    C[(size_t)rlo * Nd + col] = v;
                    if (WRITE_P) { float s = dinv[rlo]; C[0] = C[0]; P[(size_t)rlo * Nd + col] = v * s * s; }
                }
                if (rlo + 1 < M) {
                    float v = hi;
                    if (OUT_RELU) v = fmaxf(v + bout[col], 0.0f);
                    C[(size_t)(rlo + 1) * Nd + col] = v;
                    if (WRITE_P) { float s = dinv[rlo + 1]; P[(size_t)(rlo + 1) * Nd + col] = v * s * s; }
                }
            }
        }
    }
}

// ---------------------------------------------------------------------------
// Final fused head: mu/logstd GEMV (42 -> 21 each), reparam, log_softmax.
// ---------------------------------------------------------------------------
__global__ void __launch_bounds__(128)
k_final(const float* __restrict__ p5,
        const float* __restrict__ Wmu, const float* __restrict__ bmu,
        const float* __restrict__ Wls, const float* __restrict__ bls,
        const float* __restrict__ eps, float* __restrict__ out) {
    __shared__ float sWmu[42 * 21];
    __shared__ float sWls[42 * 21];
    __shared__ float sbmu[21];
    __shared__ float sbls[21];
    for (int i = threadIdx.x; i < 42 * 21; i += blockDim.x) {
        sWmu[i] = Wmu[i];
        sWls[i] = Wls[i];
    }
    if (threadIdx.x < 21) {
        sbmu[threadIdx.x] = bmu[threadIdx.x];
        sbls[threadIdx.x] = bls[threadIdx.x];
    }
    __syncthreads();

    int n = blockIdx.x * blockDim.x + threadIdx.x;
    if (n >= NN) return;

    float xr[42];
#pragma unroll
    for (int i = 0; i < 42; i++) xr[i] = p5[(size_t)n * 42 + i];

    float z[21];
#pragma unroll
    for (int j = 0; j < 21; j++) {
        float mu = sbmu[j];
        float ls = sbls[j];
#pragma unroll
        for (int i = 0; i < 42; i++) {
            mu += xr[i] * sWmu[i * 21 + j];
            ls += xr[i] * sWls[i * 21 + j];
        }
        ls = fminf(ls, 10.0f);
        z[j] = mu + eps[(size_t)n * 21 + j] * expf(ls);
    }
    float m = z[0];
#pragma unroll
    for (int j = 1; j < 21; j++) m = fmaxf(m, z[j]);
    float s = 0.0f;
#pragma unroll
    for (int j = 0; j < 21; j++) s += expf(z[j] - m);
    float lse = m + logf(s);
#pragma unroll
    for (int j = 0; j < 21; j++) out[(size_t)n * 21 + j] = z[j] - lse;
}

// ---------------------------------------------------------------------------
static inline int cdiv(long a, long b) { return (int)((a + b - 1) / b); }

extern "C" void kernel_launch(void* const* d_in, const int* in_sizes, int n_in,
                              void* d_out, int out_size) {
    const float* x    = (const float*)d_in[0];
    const int*   ei   = (const int*)  d_in[1];
    const float* eps  = (const float*)d_in[2];
    const float* W1   = (const float*)d_in[3];
    const float* b1   = (const float*)d_in[4];
    const float* W2   = (const float*)d_in[5];
    const float* b2   = (const float*)d_in[6];
    const float* W3   = (const float*)d_in[7];
    const float* b3   = (const float*)d_in[8];
    const float* W4   = (const float*)d_in[9];
    const float* b4   = (const float*)d_in[10];
    const float* Wmu  = (const float*)d_in[11];
    const float* bmu  = (const float*)d_in[12];
    const float* Wls  = (const float*)d_in[13];
    const float* bls  = (const float*)d_in[14];
    float* out = (float*)d_out;

    float *deg, *en, *xp, *p0, *a1, *t2, *p2, *t3, *p3, *t4, *p4, *a4, *p5;
    cudaGetSymbolAddress((void**)&deg, g_deg);
    cudaGetSymbolAddress((void**)&en,  g_en);
    cudaGetSymbolAddress((void**)&xp,  g_xp);
    cudaGetSymbolAddress((void**)&p0,  g_p0);
    cudaGetSymbolAddress((void**)&a1,  g_a1);
    cudaGetSymbolAddress((void**)&t2,  g_t2);
    cudaGetSymbolAddress((void**)&p2,  g_p2);
    cudaGetSymbolAddress((void**)&t3,  g_t3);
    cudaGetSymbolAddress((void**)&p3,  g_p3);
    cudaGetSymbolAddress((void**)&t4,  g_t4);
    cudaGetSymbolAddress((void**)&p4,  g_p4);
    cudaGetSymbolAddress((void**)&a4,  g_a4);
    cudaGetSymbolAddress((void**)&p5,  g_p5);

    const int* src = ei;
    const int* dst = ei + EE;

    // normalization
    k_deg_init<<<cdiv(NN, 256), 256>>>(deg);
    k_deg_count<<<cdiv(EE, 256), 256>>>(dst, deg);
    k_rsqrt<<<cdiv(NN, 256), 256>>>(deg);
    k_edge_norm<<<cdiv(EE, 256), 256>>>(src, dst, deg, en);

    // conv1: propagate x (padded to 36) first, then GEMM 35->336 (+b1, relu)
    k_pad_pinit<<<cdiv((long)NN * 36, 256), 256>>>(x, deg, xp, p0);
    k_scatter<36, 4><<<cdiv(EE, 28), 252>>>(src, dst, en, xp, p0);
    k_gemm2<false, true, false><<<dim3(cdiv(NN, 128), 6), 256>>>(
        p0, 36, nullptr, W1, b1, a1, nullptr, nullptr, NN, 35, 336);

    // conv2: transform (336->168), epilogue writes t2 and p2 = t2*dinv^2
    k_gemm2<false, false, true><<<dim3(cdiv(NN, 128), 3), 256>>>(
        a1, 336, nullptr, W2, nullptr, t2, p2, deg, NN, 336, 168);
    k_scatter<168, 4><<<cdiv(EE, 6), 252>>>(src, dst, en, t2, p2);

    // conv3: input = relu(p2 + b2) fused, 168->84, writes t3 + p3
    k_gemm2<true, false, true><<<dim3(cdiv(NN, 128), 2), 256>>>(
        p2, 168, b2, W3, nullptr, t3, p3, deg, NN, 168, 84);
    k_scatter<84, 4><<<cdiv(EE, 12), 252>>>(src, dst, en, t3, p3);

    // conv4: input = relu(p3 + b3), 84->42, writes t4 + p4
    k_gemm2<true, false, true><<<dim3(cdiv(NN, 128), 1), 256>>>(
        p3, 84, b3, W4, nullptr, t4, p4, deg, NN, 84, 42);
    k_scatter<42, 2><<<cdiv(EE, 12), 252>>>(src, dst, en, t4, p4);

    // a4 = relu(p4 + b4); p5 = a4*dinv^2; shared propagation for both heads
    k_relu_bias_pinit<<<cdiv((long)NN * 42, 256), 256>>>(p4, b4, deg, a4, p5);
    k_scatter<42, 2><<<cdiv(EE, 12), 252>>>(src, dst, en, a4, p5);

    // fused heads + reparam + log_softmax
    k_final<<<cdiv(NN, 128), 128>>>(p5, Wmu, bmu, Wls, bls, eps, out);
}

// round 3
// speedup vs baseline: 1.6699x; 1.6699x over previous
#include <cuda_runtime.h>
#include <cstdint>

#define NN 100000
#define EE 1600000
#define NPART 98   // ceil(NN/1024)

// ---------------------------------------------------------------------------
// Static device scratch
// ---------------------------------------------------------------------------
__device__ __align__(256) float g_dinv[NN];
__device__ __align__(256) float g_xx [NN * 36];     // dinv * padded x
__device__ __align__(256) float g_p0 [NN * 36];     // agg
__device__ __align__(256) float g_a1 [NN * 336];    // relu(conv1)
__device__ __align__(256) float g_tt2[NN * 168];    // dinv * (a1@W2)
__device__ __align__(256) float g_p2 [NN * 168];
__device__ __align__(256) float g_tt3[NN * 84];
__device__ __align__(256) float g_p3 [NN * 84];
__device__ __align__(256) float g_tt4[NN * 42];
__device__ __align__(256) float g_p4 [NN * 42];
__device__ __align__(256) float g_a4s[NN * 42];     // dinv * relu(p4+b4)
__device__ __align__(256) float g_p5 [NN * 42];

__device__ __align__(256) int g_cnt[NN];
__device__ __align__(256) int g_cur[NN];
__device__ __align__(256) int g_off[NN + 1];
__device__ __align__(256) int g_adj[EE];
__device__ __align__(256) int g_part[NPART];

// ---------------------------------------------------------------------------
// Packed f32x2 helpers (Blackwell FFMA2 — only via PTX)
// ---------------------------------------------------------------------------
__device__ __forceinline__ uint64_t pack2(float lo, float hi) {
    uint64_t r;
    asm("mov.b64 %0, {%1, %2};" : "=l"(r) : "f"(lo), "f"(hi));
    return r;
}
__device__ __forceinline__ void unpack2(uint64_t v, float& lo, float& hi) {
    asm("mov.b64 {%0, %1}, %2;" : "=f"(lo), "=f"(hi) : "l"(v));
}
__device__ __forceinline__ void ffma2(uint64_t& d, uint64_t a, uint64_t b) {
    asm("fma.rn.f32x2 %0, %1, %2, %3;" : "=l"(d) : "l"(a), "l"(b), "l"(d));
}

// ---------------------------------------------------------------------------
// CSR build
// ---------------------------------------------------------------------------
__global__ void k_zero2(int* cnt, int* cur) {
    int i = blockIdx.x * blockDim.x + threadIdx.x;
    if (i < NN) { cnt[i] = 0; cur[i] = 0; }
}
__global__ void k_count(const int* __restrict__ dst, int* cnt) {
    int e = blockIdx.x * blockDim.x + threadIdx.x;
    if (e < EE) atomicAdd(&cnt[dst[e]], 1);
}
__global__ void k_dinv(const int* __restrict__ cnt, float* __restrict__ dinv) {
    int i = blockIdx.x * blockDim.x + threadIdx.x;
    if (i < NN) dinv[i] = rsqrtf((float)cnt[i] + 1.0f);
}
__global__ void k_scan1(const int* __restrict__ cnt, int* __restrict__ off,
                        int* __restrict__ part) {
    __shared__ int s[1024];
    int t = threadIdx.x;
    int i = blockIdx.x * 1024 + t;
    int v = (i < NN) ? cnt[i] : 0;
    s[t] = v;
    __syncthreads();
    for (int d = 1; d < 1024; d <<= 1) {
        int u = (t >= d) ? s[t - d] : 0;
        __syncthreads();
        s[t] += u;
        __syncthreads();
    }
    if (i < NN) off[i] = s[t] - v;          // exclusive
    if (t == 1023) part[blockIdx.x] = s[1023];
}
__global__ void k_scan2(int* part, int* off) {
    if (threadIdx.x == 0 && blockIdx.x == 0) {
        int run = 0;
        for (int p = 0; p < NPART; p++) { int c = part[p]; part[p] = run; run += c; }
        off[NN] = EE;
    }
}
__global__ void k_scan3(int* __restrict__ off, const int* __restrict__ part) {
    int i = blockIdx.x * 1024 + threadIdx.x;
    if (i < NN) off[i] += part[blockIdx.x];
}
__global__ void k_fill(const int* __restrict__ src, const int* __restrict__ dst,
                       const int* __restrict__ off, int* cur, int* __restrict__ adj) {
    int e = blockIdx.x * blockDim.x + threadIdx.x;
    if (e >= EE) return;
    int d = dst[e];
    int p = off[d] + atomicAdd(&cur[d], 1);
    adj[p] = src[e];
}

// ---------------------------------------------------------------------------
// Elementwise fused kernels
// ---------------------------------------------------------------------------
// xx = dinv[n] * pad(x)[n,c]  (35 -> 36)
__global__ void k_pad_scale(const float* __restrict__ x, const float* __restrict__ dinv,
                            float* __restrict__ xx) {
    int i = blockIdx.x * blockDim.x + threadIdx.x;
    if (i >= NN * 36) return;
    int n = i / 36, c = i - n * 36;
    float v = (c < 35) ? x[(size_t)n * 35 + c] : 0.0f;
    xx[i] = v * dinv[n];
}
// a4s = dinv[n] * relu(p4 + b4)
__global__ void k_relu_bias_scale(const float* __restrict__ p4, const float* __restrict__ b4,
                                  const float* __restrict__ dinv, float* __restrict__ a4s) {
    int i = blockIdx.x * blockDim.x + threadIdx.x;
    if (i >= NN * 42) return;
    int n = i / 42;
    a4s[i] = fmaxf(p4[i] + b4[i % 42], 0.0f) * dinv[n];
}

// ---------------------------------------------------------------------------
// CSR gather aggregation: p[d] = dinv[d] * (tt[d] + sum_{s in N(d)} tt[s])
// Group of G = D/VEC lanes per node.
// ---------------------------------------------------------------------------
template <int D, int VEC>
__global__ void __launch_bounds__(252)
k_agg(const int* __restrict__ off, const int* __restrict__ adj,
      const float* __restrict__ dinv, const float* __restrict__ tt,
      float* __restrict__ p) {
    constexpr int G = D / VEC;
    constexpr int NPB = 252 / G;
    int g = threadIdx.x / G;
    int c = (threadIdx.x - g * G) * VEC;
    int node = blockIdx.x * NPB + g;
    if (node >= NN) return;
    int ib = off[node], ie = off[node + 1];
    if (VEC == 4) {
        float4 acc = *(const float4*)(tt + (size_t)node * D + c);
        for (int i = ib; i < ie; i++) {
            int s = adj[i];
            float4 v = *(const float4*)(tt + (size_t)s * D + c);
            acc.x += v.x; acc.y += v.y; acc.z += v.z; acc.w += v.w;
        }
        float sc = dinv[node];
        acc.x *= sc; acc.y *= sc; acc.z *= sc; acc.w *= sc;
        *(float4*)(p + (size_t)node * D + c) = acc;
    } else {
        float2 acc = *(const float2*)(tt + (size_t)node * D + c);
        for (int i = ib; i < ie; i++) {
            int s = adj[i];
            float2 v = *(const float2*)(tt + (size_t)s * D + c);
            acc.x += v.x; acc.y += v.y;
        }
        float sc = dinv[node];
        acc.x *= sc; acc.y *= sc;
        *(float2*)(p + (size_t)node * D + c) = acc;
    }
}

// ---------------------------------------------------------------------------
// f32x2 GEMM, 128x64 tile, 256 threads, 8x4 microtile, col-paired accums.
// A in smem duplicated {a,a} (broadcast reads); B in natural col pairs.
// IN_RELU:   a = relu(A + binA) at load
// OUT_RELU:  c = relu(c + bout)            (conv1)
// OUT_SCALE: c = c * dinv[row]             (conv2..4 -> tt)
// ---------------------------------------------------------------------------
template <bool IN_RELU, bool OUT_RELU, bool OUT_SCALE>
__global__ void __launch_bounds__(256)
k_gemm2(const float* __restrict__ A, int lda, const float* __restrict__ binA,
        const float* __restrict__ B, const float* __restrict__ bout,
        float* __restrict__ C, const float* __restrict__ dinv,
        int M, int K, int Nd) {
    __shared__ uint64_t As[16][130];   // [kk][row] = {a,a}
    __shared__ uint64_t Bs[16][34];    // [kk][colpair] = {b0,b1}

    int tid = threadIdx.x;
    int tx = tid & 15;        // 4 cols = 2 colpairs
    int ty = tid >> 4;        // 8 rows
    int row0 = blockIdx.x * 128;
    int col0 = blockIdx.y * 64;

    uint64_t acc[8][2];
#pragma unroll
    for (int i = 0; i < 8; i++) { acc[i][0] = 0ull; acc[i][1] = 0ull; }

    for (int k0 = 0; k0 < K; k0 += 16) {
#pragma unroll
        for (int l = 0; l < 8; l++) {
            int idx = tid + l * 256;
            int kk = idx & 15, rr = idx >> 4;
            int grow = row0 + rr, gk = k0 + kk;
            float a = 0.0f;
            if (grow < M && gk < K) {
                a = A[(size_t)grow * lda + gk];
                if (IN_RELU) a = fmaxf(a + binA[gk], 0.0f);
            }
            As[kk][rr] = pack2(a, a);
        }
#pragma unroll
        for (int l = 0; l < 2; l++) {
            int idx = tid + l * 256;
            int cp = idx & 31, kk = idx >> 5;
            int gk = k0 + kk, gc = col0 + 2 * cp;
            float2 bv = make_float2(0.0f, 0.0f);
            if (gk < K && gc < Nd) bv = *(const float2*)(B + (size_t)gk * Nd + gc);
            Bs[kk][cp] = pack2(bv.x, bv.y);
        }
        __syncthreads();
#pragma unroll
        for (int kk = 0; kk < 16; kk++) {
            ulonglong2 bb = *(const ulonglong2*)&Bs[kk][2 * tx];
#pragma unroll
            for (int i = 0; i < 4; i++) {
                ulonglong2 aa = *(const ulonglong2*)&As[kk][ty * 8 + 2 * i];
                ffma2(acc[2 * i][0],     aa.x, bb.x);
                ffma2(acc[2 * i][1],     aa.x, bb.y);
                ffma2(acc[2 * i + 1][0], aa.y, bb.x);
                ffma2(acc[2 * i + 1][1], aa.y, bb.y);
            }
        }
        __syncthreads();
    }

    int colb = col0 + tx * 4;
    bool fullvec = (row0 + 127 < M) && (col0 + 63 < Nd);
    if (fullvec) {
        float4 bb;
        if (OUT_RELU) bb = *(const float4*)(bout + colb);
#pragma unroll
        for (int i = 0; i < 8; i++) {
            int row = row0 + ty * 8 + i;
            float4 v;
            unpack2(acc[i][0], v.x, v.y);
            unpack2(acc[i][1], v.z, v.w);
            if (OUT_RELU) {
                v.x = fmaxf(v.x + bb.x, 0.f); v.y = fmaxf(v.y + bb.y, 0.f);
                v.z = fmaxf(v.z + bb.z, 0.f); v.w = fmaxf(v.w + bb.w, 0.f);
            }
            if (OUT_SCALE) {
                float s = dinv[row];
                v.x *= s; v.y *= s; v.z *= s; v.w *= s;
            }
            *(float4*)(C + (size_t)row * Nd + colb) = v;
        }
    } else {
#pragma unroll
        for (int i = 0; i < 8; i++) {
            int row = row0 + ty * 8 + i;
            if (row >= M) continue;
            float vv[4];
            unpack2(acc[i][0], vv[0], vv[1]);
            unpack2(acc[i][1], vv[2], vv[3]);
            float s = OUT_SCALE ? dinv[row] : 1.0f;
#pragma unroll
            for (int j = 0; j < 4; j++) {
                int col = colb + j;
                if (col >= Nd) continue;
                float v = vv[j];
                if (OUT_RELU) v = fmaxf(v + bout[col], 0.0f);
                if (OUT_SCALE) v *= s;
                C[(size_t)row * Nd + col] = v;
            }
        }
    }
}

// ---------------------------------------------------------------------------
// Final fused head: mu/logstd GEMV (42 -> 21 each), reparam, log_softmax.
// ---------------------------------------------------------------------------
__global__ void __launch_bounds__(128)
k_final(const float* __restrict__ p5,
        const float* __restrict__ Wmu, const float* __restrict__ bmu,
        const float* __restrict__ Wls, const float* __restrict__ bls,
        const float* __restrict__ eps, float* __restrict__ out) {
    __shared__ float sWmu[42 * 21];
    __shared__ float sWls[42 * 21];
    __shared__ float sbmu[21];
    __shared__ float sbls[21];
    for (int i = threadIdx.x; i < 42 * 21; i += blockDim.x) {
        sWmu[i] = Wmu[i];
        sWls[i] = Wls[i];
    }
    if (threadIdx.x < 21) {
        sbmu[threadIdx.x] = bmu[threadIdx.x];
        sbls[threadIdx.x] = bls[threadIdx.x];
    }
    __syncthreads();

    int n = blockIdx.x * blockDim.x + threadIdx.x;
    if (n >= NN) return;

    float xr[42];
#pragma unroll
    for (int i = 0; i < 42; i++) xr[i] = p5[(size_t)n * 42 + i];

    float z[21];
#pragma unroll
    for (int j = 0; j < 21; j++) {
        float mu = sbmu[j];
        float ls = sbls[j];
#pragma unroll
        for (int i = 0; i < 42; i++) {
            mu += xr[i] * sWmu[i * 21 + j];
            ls += xr[i] * sWls[i * 21 + j];
        }
        ls = fminf(ls, 10.0f);
        z[j] = mu + eps[(size_t)n * 21 + j] * expf(ls);
    }
    float m = z[0];
#pragma unroll
    for (int j = 1; j < 21; j++) m = fmaxf(m, z[j]);
    float s = 0.0f;
#pragma unroll
    for (int j = 0; j < 21; j++) s += expf(z[j] - m);
    float lse = m + logf(s);
#pragma unroll
    for (int j = 0; j < 21; j++) out[(size_t)n * 21 + j] = z[j] - lse;
}

// ---------------------------------------------------------------------------
static inline int cdiv(long a, long b) { return (int)((a + b - 1) / b); }

extern "C" void kernel_launch(void* const* d_in, const int* in_sizes, int n_in,
                              void* d_out, int out_size) {
    const float* x    = (const float*)d_in[0];
    const int*   ei   = (const int*)  d_in[1];
    const float* eps  = (const float*)d_in[2];
    const float* W1   = (const float*)d_in[3];
    const float* b1   = (const float*)d_in[4];
    const float* W2   = (const float*)d_in[5];
    const float* b2   = (const float*)d_in[6];
    const float* W3   = (const float*)d_in[7];
    const float* b3   = (const float*)d_in[8];
    const float* W4   = (const float*)d_in[9];
    const float* b4   = (const float*)d_in[10];
    const float* Wmu  = (const float*)d_in[11];
    const float* bmu  = (const float*)d_in[12];
    const float* Wls  = (const float*)d_in[13];
    const float* bls  = (const float*)d_in[14];
    float* out = (float*)d_out;

    float *dinv, *xx, *p0, *a1, *tt2, *p2, *tt3, *p3, *tt4, *p4, *a4s, *p5;
    int *cnt, *cur, *off, *adj, *part;
    cudaGetSymbolAddress((void**)&dinv, g_dinv);
    cudaGetSymbolAddress((void**)&xx,  g_xx);
    cudaGetSymbolAddress((void**)&p0,  g_p0);
    cudaGetSymbolAddress((void**)&a1,  g_a1);
    cudaGetSymbolAddress((void**)&tt2, g_tt2);
    cudaGetSymbolAddress((void**)&p2,  g_p2);
    cudaGetSymbolAddress((void**)&tt3, g_tt3);
    cudaGetSymbolAddress((void**)&p3,  g_p3);
    cudaGetSymbolAddress((void**)&tt4, g_tt4);
    cudaGetSymbolAddress((void**)&p4,  g_p4);
    cudaGetSymbolAddress((void**)&a4s, g_a4s);
    cudaGetSymbolAddress((void**)&p5,  g_p5);
    cudaGetSymbolAddress((void**)&cnt, g_cnt);
    cudaGetSymbolAddress((void**)&cur, g_cur);
    cudaGetSymbolAddress((void**)&off, g_off);
    cudaGetSymbolAddress((void**)&adj, g_adj);
    cudaGetSymbolAddress((void**)&part, g_part);

    const int* src = ei;
    const int* dst = ei + EE;

    // ---- CSR build + normalization ----
    k_zero2<<<cdiv(NN, 256), 256>>>(cnt, cur);
    k_count<<<cdiv(EE, 256), 256>>>(dst, cnt);
    k_dinv<<<cdiv(NN, 256), 256>>>(cnt, dinv);
    k_scan1<<<NPART, 1024>>>(cnt, off, part);
    k_scan2<<<1, 32>>>(part, off);
    k_scan3<<<NPART, 1024>>>(off, part);
    k_fill<<<cdiv(EE, 256), 256>>>(src, dst, off, cur, adj);

    // ---- conv1: aggregate x (D=36), then GEMM 35->336 (+b1, relu) ----
    k_pad_scale<<<cdiv((long)NN * 36, 256), 256>>>(x, dinv, xx);
    k_agg<36, 4><<<cdiv(NN, 28), 252>>>(off, adj, dinv, xx, p0);
    k_gemm2<false, true, false><<<dim3(cdiv(NN, 128), 6), 256>>>(
        p0, 36, nullptr, W1, b1, a1, nullptr, NN, 35, 336);

    // ---- conv2: GEMM 336->168 (epilogue scales by dinv), aggregate ----
    k_gemm2<false, false, true><<<dim3(cdiv(NN, 128), 3), 256>>>(
        a1, 336, nullptr, W2, nullptr, tt2, dinv, NN, 336, 168);
    k_agg<168, 4><<<cdiv(NN, 6), 252>>>(off, adj, dinv, tt2, p2);

    // ---- conv3: in = relu(p2+b2), 168->84, scaled out ----
    k_gemm2<true, false, true><<<dim3(cdiv(NN, 128), 2), 256>>>(
        p2, 168, b2, W3, nullptr, tt3, dinv, NN, 168, 84);
    k_agg<84, 4><<<cdiv(NN, 12), 252>>>(off, adj, dinv, tt3, p3);

    // ---- conv4: in = relu(p3+b3), 84->42, scaled out ----
    k_gemm2<true, false, true><<<dim3(cdiv(NN, 128), 1), 256>>>(
        p3, 84, b3, W4, nullptr, tt4, dinv, NN, 84, 42);
    k_agg<42, 2><<<cdiv(NN, 12), 252>>>(off, adj, dinv, tt4, p4);

    // ---- shared head propagation: a4s = dinv*relu(p4+b4), aggregate ----
    k_relu_bias_scale<<<cdiv((long)NN * 42, 256), 256>>>(p4, b4, dinv, a4s);
    k_agg<42, 2><<<cdiv(NN, 12), 252>>>(off, adj, dinv, a4s, p5);

    // ---- fused heads + reparam + log_softmax ----
    k_final<<<cdiv(NN, 128), 128>>>(p5, Wmu, bmu, Wls, bls, eps, out);
}